// round 8
// baseline (speedup 1.0000x reference)
#include <cuda_runtime.h>
#include <cuda_fp16.h>
#include <cstdint>

// ============================================================================
// PairwiseMLPLinkPredictor — persistent warp-specialized HMMA kernel.
//   1 CTA/SM, 512 threads: warps 0-7 = consumers (MMA), warps 8-15 = producers.
//   W1 [256n][256k] + W2 [128n][256k] fp16 swizzled images RESIDENT in smem.
//   Feats ring: 2 x [32 pairs][256k] fp16 (16KB each), mbarrier-synced.
//   Consumer per tile: MMA1 (warp 32x32) -> h1 -> MMA2 (warp 32x16) -> out.
// ============================================================================

#define NTH   512
#define TILE  32

// ---- SMEM layout (bytes), total 231488 (< 232448 max) ----
#define OFF_W1   0         // 131072
#define OFF_W2   131072    // 65536
#define OFF_F    196608    // 2 x 16384 feats ring
#define OFF_B1   229376    // 1024
#define OFF_PART 230400    // 1024 : [8 warps][32 rows]
#define OFF_MBAR 231424    // 32   : full0, full1, empty0, empty1
#define SMEM_BYTES 231488

// swizzled offset in a [rows][256] fp16 tile (512B rows, 32 chunks of 16B)
__host__ __device__ __forceinline__ uint32_t timg(int r, int k) {
    return (uint32_t)(r * 512 + ((((k >> 3) ^ (r & 7)) & 31) << 4) + ((k & 7) << 1));
}

// ---- global fp16 weight images (prep kernel output; same as R4, validated) --
__device__ __align__(1024) unsigned char g_W1h[131072];  // [256][256] swizzled
__device__ __align__(1024) unsigned char g_W2h[65536];   // [128][256] swizzled

// ---------------------------------------------------------------------------
__device__ __forceinline__ uint32_t smem_u32(const void* p) {
    uint32_t a;
    asm("{ .reg .u64 t; cvta.to.shared.u64 t, %1; cvt.u32.u64 %0, t; }" : "=r"(a) : "l"(p));
    return a;
}
__device__ __forceinline__ void ldsm_x4(uint32_t r[4], uint32_t addr) {
    asm volatile("ldmatrix.sync.aligned.m8n8.x4.shared.b16 {%0,%1,%2,%3}, [%4];"
                 : "=r"(r[0]), "=r"(r[1]), "=r"(r[2]), "=r"(r[3]) : "r"(addr));
}
__device__ __forceinline__ void mma16816(float c[4], const uint32_t a[4],
                                         uint32_t b0, uint32_t b1) {
    asm volatile("mma.sync.aligned.m16n8k16.row.col.f32.f16.f16.f32 "
                 "{%0,%1,%2,%3}, {%4,%5,%6,%7}, {%8,%9}, {%0,%1,%2,%3};"
                 : "+f"(c[0]), "+f"(c[1]), "+f"(c[2]), "+f"(c[3])
                 : "r"(a[0]), "r"(a[1]), "r"(a[2]), "r"(a[3]), "r"(b0), "r"(b1));
}
#define CP16(dst, src) \
    asm volatile("cp.async.cg.shared.global [%0], [%1], 16;" :: "r"(dst), "l"(src) : "memory")
#define CP_COMMIT() asm volatile("cp.async.commit_group;" ::: "memory")
#define CP_WAIT0()  asm volatile("cp.async.wait_group 0;" ::: "memory")

#define MBAR_INIT(a, c) \
    asm volatile("mbarrier.init.shared.b64 [%0], %1;" :: "r"(a), "r"((uint32_t)(c)) : "memory")
#define MBAR_ARRIVE(a) \
    asm volatile("mbarrier.arrive.shared.b64 _, [%0];" :: "r"(a) : "memory")
#define MBAR_WAIT(a, ph) do {                                                   \
    uint32_t _m = (a), _p = (uint32_t)(ph), _d;                                 \
    asm volatile("{\n\t.reg .pred p;\n\t"                                       \
        "mbarrier.try_wait.parity.acquire.cta.shared::cta.b64 p, [%1], %2;\n\t" \
        "selp.b32 %0, 1, 0, p;\n\t}" : "=r"(_d) : "r"(_m), "r"(_p) : "memory"); \
    if (!_d) {                                                                  \
        asm volatile("{\n\t.reg .pred P1;\n\tWL_%=:\n\t"                        \
            "mbarrier.try_wait.parity.acquire.cta.shared::cta.b64 P1, [%0], %1, 0x989680;\n\t" \
            "@P1 bra.uni WD_%=;\n\tbra.uni WL_%=;\n\tWD_%=:\n\t}"               \
            :: "r"(_m), "r"(_p) : "memory");                                    \
    } } while (0)

#define BAR_CONS() asm volatile("bar.sync 1, 256;" ::: "memory")

// ---------------------------------------------------------------------------
// Prep: W1h[n][k] = fp16(W1[k*256+n]) swizzled; W2h[n][k] = fp16(W2[k*128+n]).
// ---------------------------------------------------------------------------
__global__ void prep_kernel(const float* __restrict__ W1, const float* __restrict__ W2) {
    const int i = blockIdx.x * blockDim.x + threadIdx.x;  // 65536
    {
        const int n = i >> 8, k = i & 255;
        *(__half*)(g_W1h + timg(n, k)) = __float2half(W1[k * 256 + n]);
    }
    if (i < 32768) {
        const int n = i >> 8, k = i & 255;
        *(__half*)(g_W2h + timg(n, k)) = __float2half(W2[k * 128 + n]);
    }
}

// ---------------------------------------------------------------------------
__global__ void __launch_bounds__(NTH, 1)
pairmlp_ws_kernel(const float* __restrict__ x,
                  const float* __restrict__ b1, const float* __restrict__ b2,
                  const float* __restrict__ W3, const float* __restrict__ b3,
                  const void*  __restrict__ ep, float* __restrict__ out, int E)
{
    extern __shared__ char smem[];
    const uint32_t sb = smem_u32(smem);
    const int tid = threadIdx.x, w = tid >> 5, lane = tid & 31;

    // ---- dtype probe: int64 edge_pairs -> odd int32 words of first 1KB all 0 ----
    int probe = 0;
    if (tid < 128) probe = ((const int*)ep)[2 * tid + 1];
    const bool is32 = (__syncthreads_or(probe != 0) != 0);

    // ---- resident weights: 192KB via cp.async ----
    #pragma unroll
    for (int i = 0; i < 16; i++) {
        const int c = tid + i * NTH;                         // 8192 chunks
        CP16(sb + OFF_W1 + c * 16, g_W1h + c * 16);
    }
    #pragma unroll
    for (int i = 0; i < 8; i++) {
        const int c = tid + i * NTH;                         // 4096 chunks
        CP16(sb + OFF_W2 + c * 16, g_W2h + c * 16);
    }
    CP_COMMIT();

    if (tid < 256) ((float*)(smem + OFF_B1))[tid] = b1[tid];
    if (tid == 0) {
        MBAR_INIT(sb + OFF_MBAR + 0,  256);   // full[0]  (producer arrivals)
        MBAR_INIT(sb + OFF_MBAR + 8,  256);   // full[1]
        MBAR_INIT(sb + OFF_MBAR + 16, 256);   // empty[0] (consumer arrivals)
        MBAR_INIT(sb + OFF_MBAR + 24, 256);   // empty[1]
    }
    CP_WAIT0();
    __syncthreads();

    const int T = (E + TILE - 1) / TILE;

    if (w < 8) {
        // =========================== CONSUMERS ===========================
        const int g = lane >> 2, tig = lane & 3;
        const int arow0 = ((lane >> 3) & 1) * 8 + (lane & 7);
        const int acsel = lane >> 4;
        const int brow0 = ((lane >> 4) & 1) * 8 + (lane & 7);
        const int bcsel = (lane >> 3) & 1;
        const float* sB1 = (const float*)(smem + OFF_B1);
        float* sPart = (float*)(smem + OFF_PART);
        const float b3v = __ldg(b3);
        const float2 b2r0 = __ldg((const float2*)(b2 + w * 16 + 2 * tig));
        const float2 b2r1 = __ldg((const float2*)(b2 + w * 16 + 8 + 2 * tig));
        const float2 w3r0 = __ldg((const float2*)(W3 + w * 16 + 2 * tig));
        const float2 w3r1 = __ldg((const float2*)(W3 + w * 16 + 8 + 2 * tig));

        int stage = 0, phase = 0;
        for (int t = blockIdx.x; t < T; t += gridDim.x) {
            MBAR_WAIT(sb + OFF_MBAR + stage * 8, phase);
            const uint32_t aB = sb + OFF_F + stage * 16384;

            // ---- MMA1: 32x256x256, warp n-slice 32 ----
            float acc1[2][4][4];
            #pragma unroll
            for (int mi = 0; mi < 2; mi++)
                #pragma unroll
                for (int ni = 0; ni < 4; ni++)
                    #pragma unroll
                    for (int v = 0; v < 4; v++) acc1[mi][ni][v] = 0.0f;

            #pragma unroll
            for (int ks = 0; ks < 16; ks++) {
                uint32_t af[2][4];
                #pragma unroll
                for (int mi = 0; mi < 2; mi++) {
                    const int r = mi * 16 + arow0;
                    ldsm_x4(af[mi], aB + r * 512 + ((((2 * ks + acsel) ^ (r & 7)) & 31) << 4));
                }
                #pragma unroll
                for (int nb = 0; nb < 2; nb++) {
                    const int r = w * 32 + nb * 16 + brow0;
                    uint32_t bf[4];
                    ldsm_x4(bf, sb + OFF_W1 + r * 512 +
                                ((((2 * ks + bcsel) ^ (r & 7)) & 31) << 4));
                    #pragma unroll
                    for (int mi = 0; mi < 2; mi++) {
                        mma16816(acc1[mi][nb * 2 + 0], af[mi], bf[0], bf[1]);
                        mma16816(acc1[mi][nb * 2 + 1], af[mi], bf[2], bf[3]);
                    }
                }
            }
            BAR_CONS();   // all consumer A-reads of feats done

            // ---- epilogue 1: h1 = fp16(relu(acc1+b1)) -> same buffer ----
            #pragma unroll
            for (int mi = 0; mi < 2; mi++) {
                const int r0 = mi * 16 + g, r1 = r0 + 8;
                #pragma unroll
                for (int ni = 0; ni < 4; ni++) {
                    const int c0 = w * 32 + ni * 8 + 2 * tig;
                    const float2 bb = *(const float2*)&sB1[c0];
                    union { __half2 h; uint32_t u; } lo, hi;
                    lo.h = __floats2half2_rn(fmaxf(acc1[mi][ni][0] + bb.x, 0.0f),
                                             fmaxf(acc1[mi][ni][1] + bb.y, 0.0f));
                    hi.h = __floats2half2_rn(fmaxf(acc1[mi][ni][2] + bb.x, 0.0f),
                                             fmaxf(acc1[mi][ni][3] + bb.y, 0.0f));
                    *(uint32_t*)(smem + OFF_F + stage * 16384 + timg(r0, c0)) = lo.u;
                    *(uint32_t*)(smem + OFF_F + stage * 16384 + timg(r1, c0)) = hi.u;
                }
            }
            BAR_CONS();   // h1 visible to all consumer warps

            // ---- MMA2: 32x128x256, warp n-slice 16 ----
            float acc2[2][2][4];
            #pragma unroll
            for (int mi = 0; mi < 2; mi++)
                #pragma unroll
                for (int nb = 0; nb < 2; nb++)
                    #pragma unroll
                    for (int v = 0; v < 4; v++) acc2[mi][nb][v] = 0.0f;

            #pragma unroll
            for (int ks = 0; ks < 16; ks++) {
                uint32_t af[2][4];
                #pragma unroll
                for (int mi = 0; mi < 2; mi++) {
                    const int r = mi * 16 + arow0;
                    ldsm_x4(af[mi], aB + r * 512 + ((((2 * ks + acsel) ^ (r & 7)) & 31) << 4));
                }
                const int r = w * 16 + brow0;
                uint32_t bf[4];
                ldsm_x4(bf, sb + OFF_W2 + r * 512 +
                            ((((2 * ks + bcsel) ^ (r & 7)) & 31) << 4));
                #pragma unroll
                for (int mi = 0; mi < 2; mi++) {
                    mma16816(acc2[mi][0], af[mi], bf[0], bf[1]);
                    mma16816(acc2[mi][1], af[mi], bf[2], bf[3]);
                }
            }
            MBAR_ARRIVE(sb + OFF_MBAR + 16 + stage * 8);   // buffer free

            // ---- layer 3: partials + store ----
            #pragma unroll
            for (int mi = 0; mi < 2; mi++) {
                float s0 = fmaxf(acc2[mi][0][0] + b2r0.x, 0.0f) * w3r0.x
                         + fmaxf(acc2[mi][0][1] + b2r0.y, 0.0f) * w3r0.y
                         + fmaxf(acc2[mi][1][0] + b2r1.x, 0.0f) * w3r1.x
                         + fmaxf(acc2[mi][1][1] + b2r1.y, 0.0f) * w3r1.y;
                float s1 = fmaxf(acc2[mi][0][2] + b2r0.x, 0.0f) * w3r0.x
                         + fmaxf(acc2[mi][0][3] + b2r0.y, 0.0f) * w3r0.y
                         + fmaxf(acc2[mi][1][2] + b2r1.x, 0.0f) * w3r1.x
                         + fmaxf(acc2[mi][1][3] + b2r1.y, 0.0f) * w3r1.y;
                s0 += __shfl_xor_sync(0xffffffffu, s0, 1);
                s0 += __shfl_xor_sync(0xffffffffu, s0, 2);
                s1 += __shfl_xor_sync(0xffffffffu, s1, 1);
                s1 += __shfl_xor_sync(0xffffffffu, s1, 2);
                if (tig == 0) {
                    sPart[w * 32 + mi * 16 + g]     = s0;
                    sPart[w * 32 + mi * 16 + 8 + g] = s1;
                }
            }
            BAR_CONS();
            if (tid < 32) {
                const long long e = (long long)t * TILE + lane;
                if (e < E) {
                    float s = b3v;
                    #pragma unroll
                    for (int ww = 0; ww < 8; ww++) s += sPart[ww * 32 + lane];
                    out[e] = s;
                }
            }
            BAR_CONS();   // sPart reusable

            stage ^= 1;
            if (stage == 0) phase ^= 1;
        }
    } else {
        // =========================== PRODUCERS ===========================
        const int ptid = tid - 256;
        const int p = ptid >> 3, sub = ptid & 7;
        const int k0 = sub * 32;

        int stage = 0, phase = 1;   // fresh barrier: parity-1 wait passes
        for (int t = blockIdx.x; t < T; t += gridDim.x) {
            MBAR_WAIT(sb + OFF_MBAR + 16 + stage * 8, phase);

            const long long e = (long long)t * TILE + p;
            long long ia = 0, ib = 0;
            if (e < (long long)E) {
                if (is32) { ia = ((const int*)ep)[2 * e];       ib = ((const int*)ep)[2 * e + 1]; }
                else      { ia = ((const long long*)ep)[2 * e]; ib = ((const long long*)ep)[2 * e + 1]; }
            }
            const float* xa = x + (size_t)ia * 256;
            const float* xb = x + (size_t)ib * 256;
            char* fb = smem + OFF_F + stage * 16384;

            #pragma unroll
            for (int j = 0; j < 4; j++) {
                const int k = k0 + 8 * j;
                float4 a0 = __ldg((const float4*)(xa + k));
                float4 a1 = __ldg((const float4*)(xa + k + 4));
                float4 c0 = __ldg((const float4*)(xb + k));
                float4 c1 = __ldg((const float4*)(xb + k + 4));
                union { __half2 h; uint32_t u; } q0, q1, q2, q3;
                q0.h = __floats2half2_rn(a0.x * c0.x, a0.y * c0.y);
                q1.h = __floats2half2_rn(a0.z * c0.z, a0.w * c0.w);
                q2.h = __floats2half2_rn(a1.x * c1.x, a1.y * c1.y);
                q3.h = __floats2half2_rn(a1.z * c1.z, a1.w * c1.w);
                *(uint4*)(fb + timg(p, k)) = make_uint4(q0.u, q1.u, q2.u, q3.u);
            }
            MBAR_ARRIVE(sb + OFF_MBAR + stage * 8);   // full

            stage ^= 1;
            if (stage == 0) phase ^= 1;
        }
    }
}

// ---------------------------------------------------------------------------
extern "C" void kernel_launch(void* const* d_in, const int* in_sizes, int n_in,
                              void* d_out, int out_size)
{
    const float* x  = (const float*)d_in[0];
    const float* W1 = (const float*)d_in[1];
    const float* b1 = (const float*)d_in[2];
    const float* W2 = (const float*)d_in[3];
    const float* b2 = (const float*)d_in[4];
    const float* W3 = (const float*)d_in[5];
    const float* b3 = (const float*)d_in[6];
    // d_in[7] = edge_index (unused)
    const void*  ep = d_in[8];
    float* out = (float*)d_out;

    const int E = out_size;
    const int T = (E + TILE - 1) / TILE;

    prep_kernel<<<256, 256>>>(W1, W2);

    int dev = 0, sms = 148;
    cudaGetDevice(&dev);
    cudaDeviceGetAttribute(&sms, cudaDevAttrMultiProcessorCount, dev);
    const int grid = sms < T ? sms : T;

    cudaFuncSetAttribute(pairmlp_ws_kernel,
                         cudaFuncAttributeMaxDynamicSharedMemorySize, SMEM_BYTES);
    pairmlp_ws_kernel<<<grid, NTH, SMEM_BYTES>>>(x, b1, b2, W3, b3, ep, out, E);
}